// round 4
// baseline (speedup 1.0000x reference)
#include <cuda_runtime.h>
#include <math.h>
#include <cstdint>

#define B 64
#define S 4096
#define E 512
#define D 512
#define H 512
#define NEGV (-1.0e9f)

// ---------------------------------------------------------------------------
// Scratch (no cudaMalloc allowed)
// ---------------------------------------------------------------------------
__device__ float g_decoded[B * H];            // 128 KB
__device__ float g_attn_part[B * 32 * E];     // 4 MB
// W_enc^T split hi/lo, packed in mma-fragment order:
// float4 { hi(k), hi(k+4), lo(k), lo(k+4) } at index (k8*64 + n8)*32 + lane
__device__ float4 g_WB[64 * 64 * 32];         // 2 MB

// ---------------------------------------------------------------------------
// helpers
// ---------------------------------------------------------------------------
__device__ __forceinline__ float tf32_rnd(float x) {
    float r;
    asm("cvt.rna.tf32.f32 %0, %1;" : "=f"(r) : "f"(x));
    return r;
}
__device__ __forceinline__ float tanh_fast(float x) {
    float e;
    asm("ex2.approx.f32 %0, %1;" : "=f"(e) : "f"(x * 2.8853900817779268f));
    float r;
    asm("rcp.approx.f32 %0, %1;" : "=f"(r) : "f"(e + 1.0f));
    return fmaf(-2.0f, r, 1.0f);
}
#define MMA_TF32(d, a, b0, b1) \
    asm volatile( \
        "mma.sync.aligned.m16n8k8.row.col.f32.tf32.tf32.f32 " \
        "{%0,%1,%2,%3}, {%4,%5,%6,%7}, {%8,%9}, {%0,%1,%2,%3};" \
        : "+f"((d)[0]), "+f"((d)[1]), "+f"((d)[2]), "+f"((d)[3]) \
        : "r"((a)[0]), "r"((a)[1]), "r"((a)[2]), "r"((a)[3]), \
          "r"(b0), "r"(b1))

// ---------------------------------------------------------------------------
// Kernel 0: W_enc [E,H] -> g_WB (transposed, tf32 hi/lo, fragment order)
// ---------------------------------------------------------------------------
__global__ void wsplit_kernel(const float* __restrict__ W_enc) {
    int idx = blockIdx.x * 256 + threadIdx.x;   // 131072 total
    int lane = idx & 31;
    int n8   = (idx >> 5) & 63;
    int k8   = idx >> 11;
    int k = k8 * 8 + (lane & 3);
    int n = n8 * 8 + (lane >> 2);
    float v0 = W_enc[k * H + n];
    float v1 = W_enc[(k + 4) * H + n];
    float h0 = tf32_rnd(v0), h1 = tf32_rnd(v1);
    float4 o;
    o.x = h0; o.y = h1;
    o.z = tf32_rnd(v0 - h0); o.w = tf32_rnd(v1 - h1);
    g_WB[idx] = o;
}

// ---------------------------------------------------------------------------
// Kernel 1: decoded[b,h] = dec[b,:] @ W_dec[:,h]
// ---------------------------------------------------------------------------
__global__ void decode_kernel(const float* __restrict__ dec,
                              const float* __restrict__ W_dec) {
    int b = blockIdx.x;
    int t = threadIdx.x;
    __shared__ float ds[D];
    ds[t] = dec[b * D + t];
    __syncthreads();
    float sum = 0.f;
#pragma unroll 8
    for (int d = 0; d < D; d++) sum += ds[d] * W_dec[d * H + t];
    g_decoded[b * H + t] = sum;
}

// ---------------------------------------------------------------------------
// Kernel 2: logits via mma.sync tf32x3
// grid = B*(S/128) = 2048 blocks, 256 threads (8 warps: 2 m-warps x 4 n-warps)
// block tile: M=128 rows, N in 4 chunks of 128 cols, K=512
// A hi/lo presplit into smem at staging; warp tile 64(m) x 32(n)
// ---------------------------------------------------------------------------
// dynamic smem layout (floats):
//   [0      .. 8192)   sA_hi[2][128*32]
//   [8192   .. 16384)  sA_lo[2][128*32]
//   [16384  .. 16896)  s_dec
//   [16896  .. 17408)  s_wout
//   [17408  .. 17920)  s_part[4][128]
#define SMF_TOTAL (17920 * 4)

__global__ void __launch_bounds__(256, 1)
logits_mma_kernel(const float* __restrict__ enc,
                  const float* __restrict__ W_out,
                  float* __restrict__ logits) {
    extern __shared__ float sm[];
    float* sAhi   = sm;            // [2][4096]
    float* sAlo   = sm + 8192;     // [2][4096]
    float* s_dec  = sm + 16384;
    float* s_wout = sm + 16896;
    float* s_part = sm + 17408;

    int tid = threadIdx.x;
    int lane = tid & 31;
    int wid = tid >> 5;
    int mw = wid & 1;     // 0..1 -> rows mw*64..
    int nw = wid >> 1;    // 0..3 -> cols nw*32 within the 128-col chunk

    int b  = blockIdx.x >> 5;
    int st = blockIdx.x & 31;
    long rowbase = (long)b * S + (long)st * 128;
    const float* encBase = enc + rowbase * E;

    for (int i = tid; i < H; i += 256) {
        s_dec[i]  = g_decoded[b * H + i];
        s_wout[i] = W_out[i];
    }

    // staging row/col for this thread (4 float4s per thread per chunk)
    int srow[4], skw[4];
#pragma unroll
    for (int it = 0; it < 4; it++) {
        int fidx = tid + it * 256;
        srow[it] = fidx >> 3;
        skw[it]  = fidx & 7;
    }

    const float4* gB = g_WB;
    float rowsum[8];
#pragma unroll
    for (int i = 0; i < 8; i++) rowsum[i] = 0.f;

    for (int nc = 0; nc < 4; nc++) {
        float acc[4][4][4];
#pragma unroll
        for (int mi = 0; mi < 4; mi++)
#pragma unroll
            for (int j = 0; j < 4; j++)
#pragma unroll
                for (int r = 0; r < 4; r++) acc[mi][j][r] = 0.f;

        int n8base = nc * 16 + nw * 4;

        // prime B for k8 = 0
        uint4 bc[4];
#pragma unroll
        for (int j = 0; j < 4; j++)
            bc[j] = *(const uint4*)&gB[(n8base + j) * 32 + lane];

        // prologue: stage kc = 0
        {
            float4 pf[4];
#pragma unroll
            for (int it = 0; it < 4; it++)
                pf[it] = *(const float4*)(encBase + (long)srow[it] * E + skw[it] * 4);
#pragma unroll
            for (int it = 0; it < 4; it++) {
                int widx = srow[it] * 32 + ((skw[it] ^ (srow[it] & 7)) << 2);
                float4 v = pf[it];
                float4 hi, lo;
                hi.x = tf32_rnd(v.x); lo.x = tf32_rnd(v.x - hi.x);
                hi.y = tf32_rnd(v.y); lo.y = tf32_rnd(v.y - hi.y);
                hi.z = tf32_rnd(v.z); lo.z = tf32_rnd(v.z - hi.z);
                hi.w = tf32_rnd(v.w); lo.w = tf32_rnd(v.w - hi.w);
                *(float4*)&sAhi[widx] = hi;
                *(float4*)&sAlo[widx] = lo;
            }
        }
        __syncthreads();

        for (int kc = 0; kc < 16; kc++) {
            float4 pf[4];
            if (kc < 15) {
#pragma unroll
                for (int it = 0; it < 4; it++)
                    pf[it] = *(const float4*)(encBase + (long)srow[it] * E +
                                              (kc + 1) * 32 + skw[it] * 4);
            }
            const float* Ah = sAhi + (kc & 1) * 4096;
            const float* Al = sAlo + (kc & 1) * 4096;

#pragma unroll
            for (int kk = 0; kk < 4; kk++) {
                int k8 = kc * 4 + kk;
                // prefetch B for next k8
                uint4 bn[4];
                int k8n = (k8 + 1 < 64) ? k8 + 1 : 63;
#pragma unroll
                for (int j = 0; j < 4; j++)
                    bn[j] = *(const uint4*)&gB[(k8n * 64 + n8base + j) * 32 + lane];

                // A fragments from presplit smem
                uint32_t aH[4][4], aL[4][4];
                int c0 = kk * 8 + (lane & 3);
                int sw0 = ((kk * 2) ^ 0), dummy; (void)dummy;
#pragma unroll
                for (int mi = 0; mi < 4; mi++) {
                    int r0 = mw * 64 + mi * 16 + (lane >> 2);
                    int i00 = r0 * 32 + ((((c0 >> 2) ^ (r0 & 7)) << 2) | (c0 & 3));
                    int r1 = r0 + 8;
                    int i10 = r1 * 32 + ((((c0 >> 2) ^ (r1 & 7)) << 2) | (c0 & 3));
                    int c1 = c0 + 4;
                    int i01 = r0 * 32 + ((((c1 >> 2) ^ (r0 & 7)) << 2) | (c1 & 3));
                    int i11 = r1 * 32 + ((((c1 >> 2) ^ (r1 & 7)) << 2) | (c1 & 3));
                    aH[mi][0] = __float_as_uint(Ah[i00]);
                    aH[mi][1] = __float_as_uint(Ah[i10]);
                    aH[mi][2] = __float_as_uint(Ah[i01]);
                    aH[mi][3] = __float_as_uint(Ah[i11]);
                    aL[mi][0] = __float_as_uint(Al[i00]);
                    aL[mi][1] = __float_as_uint(Al[i10]);
                    aL[mi][2] = __float_as_uint(Al[i01]);
                    aL[mi][3] = __float_as_uint(Al[i11]);
                }
                (void)sw0;

#pragma unroll
                for (int mi = 0; mi < 4; mi++)
#pragma unroll
                    for (int j = 0; j < 4; j++)
                        MMA_TF32(acc[mi][j], aH[mi], bc[j].x, bc[j].y);
#pragma unroll
                for (int mi = 0; mi < 4; mi++)
#pragma unroll
                    for (int j = 0; j < 4; j++)
                        MMA_TF32(acc[mi][j], aL[mi], bc[j].x, bc[j].y);
#pragma unroll
                for (int mi = 0; mi < 4; mi++)
#pragma unroll
                    for (int j = 0; j < 4; j++)
                        MMA_TF32(acc[mi][j], aH[mi], bc[j].z, bc[j].w);

#pragma unroll
                for (int j = 0; j < 4; j++) bc[j] = bn[j];
            }

            if (kc < 15) {
                float* Whn = sAhi + ((kc + 1) & 1) * 4096;
                float* Wln = sAlo + ((kc + 1) & 1) * 4096;
#pragma unroll
                for (int it = 0; it < 4; it++) {
                    int widx = srow[it] * 32 + ((skw[it] ^ (srow[it] & 7)) << 2);
                    float4 v = pf[it];
                    float4 hi, lo;
                    hi.x = tf32_rnd(v.x); lo.x = tf32_rnd(v.x - hi.x);
                    hi.y = tf32_rnd(v.y); lo.y = tf32_rnd(v.y - hi.y);
                    hi.z = tf32_rnd(v.z); lo.z = tf32_rnd(v.z - hi.z);
                    hi.w = tf32_rnd(v.w); lo.w = tf32_rnd(v.w - hi.w);
                    *(float4*)&Whn[widx] = hi;
                    *(float4*)&Wln[widx] = lo;
                }
            }
            __syncthreads();
        }

        // epilogue for this N-chunk: tanh(acc + dec) * wout -> rowsum
#pragma unroll
        for (int mi = 0; mi < 4; mi++)
#pragma unroll
            for (int j = 0; j < 4; j++)
#pragma unroll
                for (int r = 0; r < 4; r++) {
                    int col = nc * 128 + nw * 32 + j * 8 + (lane & 3) * 2 + (r & 1);
                    float x = acc[mi][j][r] + s_dec[col];
                    rowsum[mi * 2 + (r >> 1)] += tanh_fast(x) * s_wout[col];
                }
    }

    // reduce over lane&3 (cols within quad)
#pragma unroll
    for (int i = 0; i < 8; i++) {
        float v = rowsum[i];
        v += __shfl_xor_sync(0xffffffffu, v, 1);
        v += __shfl_xor_sync(0xffffffffu, v, 2);
        rowsum[i] = v;
    }
    if ((lane & 3) == 0) {
#pragma unroll
        for (int i = 0; i < 8; i++) {
            int mi = i >> 1;
            int row = mw * 64 + mi * 16 + (lane >> 2) + (i & 1) * 8;
            s_part[nw * 128 + row] = rowsum[i];
        }
    }
    __syncthreads();
    if (tid < 128)
        logits[rowbase + tid] = (s_part[tid] + s_part[128 + tid]) +
                                (s_part[256 + tid] + s_part[384 + tid]);
}

// ---------------------------------------------------------------------------
// Kernel 3: masked softmax over S, in place
// ---------------------------------------------------------------------------
__global__ void softmax_kernel(const int* __restrict__ mask,
                               float* __restrict__ probs) {
    int b = blockIdx.x;
    int t = threadIdx.x;
    __shared__ float red[32];
    float l[4];
#pragma unroll
    for (int i = 0; i < 4; i++) {
        int s = t + i * 1024;
        float v = probs[(long)b * S + s];
        l[i] = (mask[(long)b * S + s] == 0) ? NEGV : v;
    }
    float m = fmaxf(fmaxf(l[0], l[1]), fmaxf(l[2], l[3]));
#pragma unroll
    for (int off = 16; off > 0; off >>= 1)
        m = fmaxf(m, __shfl_xor_sync(0xffffffffu, m, off));
    if ((t & 31) == 0) red[t >> 5] = m;
    __syncthreads();
    if (t < 32) {
        float v = red[t];
#pragma unroll
        for (int off = 16; off > 0; off >>= 1)
            v = fmaxf(v, __shfl_xor_sync(0xffffffffu, v, off));
        red[t] = v;
    }
    __syncthreads();
    m = red[0];
    __syncthreads();
    float e[4];
    float sum = 0.f;
#pragma unroll
    for (int i = 0; i < 4; i++) { e[i] = expf(l[i] - m); sum += e[i]; }
#pragma unroll
    for (int off = 16; off > 0; off >>= 1)
        sum += __shfl_xor_sync(0xffffffffu, sum, off);
    if ((t & 31) == 0) red[t >> 5] = sum;
    __syncthreads();
    if (t < 32) {
        float v = red[t];
#pragma unroll
        for (int off = 16; off > 0; off >>= 1)
            v += __shfl_xor_sync(0xffffffffu, v, off);
        red[t] = v;
    }
    __syncthreads();
    float inv = 1.f / red[0];
#pragma unroll
    for (int i = 0; i < 4; i++)
        probs[(long)b * S + t + i * 1024] = e[i] * inv;
}

// ---------------------------------------------------------------------------
// Kernel 4: partial attn over 128-row s-chunks, float4 per thread
// grid = B*32, 128 threads
// ---------------------------------------------------------------------------
__global__ void attn_part_kernel(const float* __restrict__ enc,
                                 const float* __restrict__ probs) {
    int sc = blockIdx.x & 31;
    int b  = blockIdx.x >> 5;
    int t  = threadIdx.x;   // 0..127, e4 index
    __shared__ float p_s[128];
    p_s[t] = probs[(long)b * S + sc * 128 + t];
    __syncthreads();
    const float4* encp = (const float4*)(enc + ((long)b * S + (long)sc * 128) * E) + t;
    float4 acc = make_float4(0.f, 0.f, 0.f, 0.f);
#pragma unroll 8
    for (int s = 0; s < 128; s++) {
        float4 v = encp[(long)s * (E / 4)];
        float p = p_s[s];
        acc.x += p * v.x; acc.y += p * v.y;
        acc.z += p * v.z; acc.w += p * v.w;
    }
    ((float4*)g_attn_part)[((long)b * 32 + sc) * (E / 4) + t] = acc;
}

// ---------------------------------------------------------------------------
// Kernel 5: fixed-order reduction -> attn (float4)
// ---------------------------------------------------------------------------
__global__ void attn_reduce_kernel(float* __restrict__ attn) {
    int b = blockIdx.x;
    int t = threadIdx.x;   // 0..127
    float4 s = make_float4(0.f, 0.f, 0.f, 0.f);
#pragma unroll
    for (int c = 0; c < 32; c++) {
        float4 v = ((const float4*)g_attn_part)[((long)b * 32 + c) * (E / 4) + t];
        s.x += v.x; s.y += v.y; s.z += v.z; s.w += v.w;
    }
    ((float4*)attn)[b * (E / 4) + t] = s;
}

// ---------------------------------------------------------------------------
extern "C" void kernel_launch(void* const* d_in, const int* in_sizes, int n_in,
                              void* d_out, int out_size) {
    const float* enc   = (const float*)d_in[0];
    const float* dec   = (const float*)d_in[1];
    const int*   mask  = (const int*)  d_in[2];
    const float* W_enc = (const float*)d_in[3];
    const float* W_dec = (const float*)d_in[4];
    const float* W_out = (const float*)d_in[5];

    float* attn  = (float*)d_out;       // [B,E]
    float* probs = attn + B * E;        // [B,S] (logits written in place)

    static int smem_set = 0;
    if (!smem_set) {
        cudaFuncSetAttribute(logits_mma_kernel,
                             cudaFuncAttributeMaxDynamicSharedMemorySize, SMF_TOTAL);
        smem_set = 1;
    }

    wsplit_kernel<<<512, 256>>>(W_enc);
    decode_kernel<<<B, 512>>>(dec, W_dec);
    logits_mma_kernel<<<B * (S / 128), 256, SMF_TOTAL>>>(enc, W_out, probs);
    softmax_kernel<<<B, 1024>>>(mask, probs);
    attn_part_kernel<<<B * 32, 128>>>(enc, probs);
    attn_reduce_kernel<<<B, 128>>>(attn);
}

// round 5
// speedup vs baseline: 1.0044x; 1.0044x over previous
#include <cuda_runtime.h>
#include <math.h>
#include <cstdint>

#define B 64
#define S 4096
#define E 512
#define D 512
#define H 512
#define NEGV (-1.0e9f)

// ---------------------------------------------------------------------------
// Scratch (no cudaMalloc allowed)
// ---------------------------------------------------------------------------
__device__ float g_decoded[B * H];            // 128 KB
__device__ float g_attn_part[B * 32 * E];     // 4 MB
// W_enc^T split hi/lo, packed in mma-fragment order:
// float4 { hi(k), hi(k+4), lo(k), lo(k+4) } at index (k8*64 + n8)*32 + lane
__device__ float4 g_WB[64 * 64 * 32];         // 2 MB

// ---------------------------------------------------------------------------
// helpers
// ---------------------------------------------------------------------------
__device__ __forceinline__ uint32_t smem_u32(const void* p) {
    uint32_t a;
    asm("{ .reg .u64 t; cvta.to.shared.u64 t, %1; cvt.u32.u64 %0, t; }"
        : "=r"(a) : "l"(p));
    return a;
}
__device__ __forceinline__ float tf32_rnd(float x) {
    float r;
    asm("cvt.rna.tf32.f32 %0, %1;" : "=f"(r) : "f"(x));
    return r;
}
__device__ __forceinline__ float tanh_fast(float x) {
    float e;
    asm("ex2.approx.f32 %0, %1;" : "=f"(e) : "f"(x * 2.8853900817779268f));
    float r;
    asm("rcp.approx.f32 %0, %1;" : "=f"(r) : "f"(e + 1.0f));
    return fmaf(-2.0f, r, 1.0f);
}
#define MMA_TF32(d, a, b0, b1) \
    asm volatile( \
        "mma.sync.aligned.m16n8k8.row.col.f32.tf32.tf32.f32 " \
        "{%0,%1,%2,%3}, {%4,%5,%6,%7}, {%8,%9}, {%0,%1,%2,%3};" \
        : "+f"((d)[0]), "+f"((d)[1]), "+f"((d)[2]), "+f"((d)[3]) \
        : "r"((a)[0]), "r"((a)[1]), "r"((a)[2]), "r"((a)[3]), \
          "r"(b0), "r"(b1))

#define CP_ASYNC16(dst, src) \
    asm volatile("cp.async.cg.shared.global [%0], [%1], 16;" \
                 :: "r"(dst), "l"(src) : "memory")
#define CP_COMMIT()  asm volatile("cp.async.commit_group;" ::: "memory")
#define CP_WAIT(n)   asm volatile("cp.async.wait_group %0;" :: "n"(n) : "memory")

// A smem swizzle: float index for logical (row, col) in a 128x32 tile
__device__ __forceinline__ int a_idx(int r, int c) {
    return r * 32 + ((((c >> 2) ^ (r & 7)) << 2) | (c & 3));
}

// ---------------------------------------------------------------------------
// Kernel 0: W_enc [E,H] -> g_WB (transposed, tf32 hi/lo, fragment order)
// ---------------------------------------------------------------------------
__global__ void wsplit_kernel(const float* __restrict__ W_enc) {
    int idx = blockIdx.x * 256 + threadIdx.x;   // 131072 total
    int lane = idx & 31;
    int n8   = (idx >> 5) & 63;
    int k8   = idx >> 11;
    int k = k8 * 8 + (lane & 3);
    int n = n8 * 8 + (lane >> 2);
    float v0 = W_enc[k * H + n];
    float v1 = W_enc[(k + 4) * H + n];
    float h0 = tf32_rnd(v0), h1 = tf32_rnd(v1);
    float4 o;
    o.x = h0; o.y = h1;
    o.z = tf32_rnd(v0 - h0); o.w = tf32_rnd(v1 - h1);
    g_WB[idx] = o;
}

// ---------------------------------------------------------------------------
// Kernel 1: decoded[b,h] = dec[b,:] @ W_dec[:,h]
// ---------------------------------------------------------------------------
__global__ void decode_kernel(const float* __restrict__ dec,
                              const float* __restrict__ W_dec) {
    int b = blockIdx.x;
    int t = threadIdx.x;
    __shared__ float ds[D];
    ds[t] = dec[b * D + t];
    __syncthreads();
    float sum = 0.f;
#pragma unroll 8
    for (int d = 0; d < D; d++) sum += ds[d] * W_dec[d * H + t];
    g_decoded[b * H + t] = sum;
}

// ---------------------------------------------------------------------------
// Kernel 2: logits via mma.sync tf32x3, B staged in smem
// grid = B*(S/128) = 2048 blocks, 256 threads (8 warps: 4 m-warps x 2 n-warps)
// block tile: M=128 rows, N in 4 chunks of 128 cols, K=512
// ---------------------------------------------------------------------------
// dynamic smem (floats):
//   [0     ..  8192)  sA[2][128*32]       raw fp32, xor-swizzled
//   [8192  .. 24576)  sB[2][4*16*32*4]    fragment-order float4 (hi,hi,lo,lo)
//   [24576 .. 25088)  s_dec
//   [25088 .. 25600)  s_wout
//   [25600 .. 25856)  s_part[2][128]
#define SMF_TOTAL (25856 * 4)

__global__ void __launch_bounds__(256, 1)
logits_mma_kernel(const float* __restrict__ enc,
                  const float* __restrict__ W_out,
                  float* __restrict__ logits) {
    extern __shared__ float sm[];
    float* sA     = sm;             // [2][4096]
    float* sB     = sm + 8192;      // [2][8192]
    float* s_dec  = sm + 24576;
    float* s_wout = sm + 25088;
    float* s_part = sm + 25600;

    int tid = threadIdx.x;
    int lane = tid & 31;
    int wid = tid >> 5;
    int mw = wid & 3;     // 0..3  -> rows mw*32..
    int nw = wid >> 2;    // 0..1  -> n8 offset nw*8 within chunk

    int b  = blockIdx.x >> 5;
    int st = blockIdx.x & 31;
    long rowbase = (long)b * S + (long)st * 128;
    const float* encBase = enc + rowbase * E;

    for (int i = tid; i < H; i += 256) {
        s_dec[i]  = g_decoded[b * H + i];
        s_wout[i] = W_out[i];
    }

    // stage one (A 128x32, B 4k8 x 16n8) chunk into buffer `buf`
    auto stage = [&](int nc, int kc, int buf) {
        // A: 4 float4 per thread
#pragma unroll
        for (int it = 0; it < 4; it++) {
            int fidx = tid + it * 256;
            int row = fidx >> 3;
            int kw  = fidx & 7;
            const float* src = encBase + (long)row * E + kc * 32 + kw * 4;
            uint32_t dst = smem_u32(&sA[buf * 4096 + row * 32 +
                                        ((kw ^ (row & 7)) << 2)]);
            CP_ASYNC16(dst, src);
        }
        // B: 8 float4 per thread (2048 total = 4 k8 x 16 n8 x 32 lanes)
#pragma unroll
        for (int it = 0; it < 8; it++) {
            int f = tid + it * 256;
            int k8rel = f >> 9;
            int n8rel = (f >> 5) & 15;
            const float4* src = &g_WB[((kc * 4 + k8rel) * 64 +
                                       nc * 16 + n8rel) * 32 + lane];
            uint32_t dst = smem_u32(&sB[buf * 8192 + f * 4]);
            CP_ASYNC16(dst, (const float*)src);
        }
        CP_COMMIT();
    };

    float rowsum[4] = {0.f, 0.f, 0.f, 0.f};

    for (int nc = 0; nc < 4; nc++) {
        float acc[2][8][4];
#pragma unroll
        for (int mi = 0; mi < 2; mi++)
#pragma unroll
            for (int j = 0; j < 8; j++)
#pragma unroll
                for (int r = 0; r < 4; r++) acc[mi][j][r] = 0.f;

        stage(nc, 0, 0);

        for (int kc = 0; kc < 16; kc++) {
            if (kc < 15) { stage(nc, kc + 1, (kc + 1) & 1); CP_WAIT(1); }
            else         { CP_WAIT(0); }
            __syncthreads();
            const float* A  = sA + (kc & 1) * 4096;
            const float* Bs = sB + (kc & 1) * 8192;

#pragma unroll
            for (int kk = 0; kk < 4; kk++) {
                // B fragments from smem (conflict-free LDS.128)
                uint4 bc[8];
#pragma unroll
                for (int j = 0; j < 8; j++)
                    bc[j] = *(const uint4*)&Bs[((kk * 16 + nw * 8 + j) * 32 +
                                                lane) * 4];

                // A fragments (hi & lo) for 2 m16 tiles, split in regs
                uint32_t aH[2][4], aL[2][4];
#pragma unroll
                for (int mi = 0; mi < 2; mi++) {
                    int r0 = mw * 32 + mi * 16 + (lane >> 2);
                    int c0 = kk * 8 + (lane & 3);
                    float v0 = A[a_idx(r0,     c0)];
                    float v1 = A[a_idx(r0 + 8, c0)];
                    float v2 = A[a_idx(r0,     c0 + 4)];
                    float v3 = A[a_idx(r0 + 8, c0 + 4)];
                    float h0 = tf32_rnd(v0), h1 = tf32_rnd(v1);
                    float h2 = tf32_rnd(v2), h3 = tf32_rnd(v3);
                    aH[mi][0] = __float_as_uint(h0);
                    aH[mi][1] = __float_as_uint(h1);
                    aH[mi][2] = __float_as_uint(h2);
                    aH[mi][3] = __float_as_uint(h3);
                    aL[mi][0] = __float_as_uint(tf32_rnd(v0 - h0));
                    aL[mi][1] = __float_as_uint(tf32_rnd(v1 - h1));
                    aL[mi][2] = __float_as_uint(tf32_rnd(v2 - h2));
                    aL[mi][3] = __float_as_uint(tf32_rnd(v3 - h3));
                }

#pragma unroll
                for (int mi = 0; mi < 2; mi++)
#pragma unroll
                    for (int j = 0; j < 8; j++)
                        MMA_TF32(acc[mi][j], aH[mi], bc[j].x, bc[j].y);
#pragma unroll
                for (int mi = 0; mi < 2; mi++)
#pragma unroll
                    for (int j = 0; j < 8; j++)
                        MMA_TF32(acc[mi][j], aL[mi], bc[j].x, bc[j].y);
#pragma unroll
                for (int mi = 0; mi < 2; mi++)
#pragma unroll
                    for (int j = 0; j < 8; j++)
                        MMA_TF32(acc[mi][j], aH[mi], bc[j].z, bc[j].w);
            }
            __syncthreads();
        }

        // epilogue for this N-chunk
#pragma unroll
        for (int mi = 0; mi < 2; mi++)
#pragma unroll
            for (int j = 0; j < 8; j++)
#pragma unroll
                for (int r = 0; r < 4; r++) {
                    int col = nc * 128 + nw * 64 + j * 8 + (lane & 3) * 2 + (r & 1);
                    float x = acc[mi][j][r] + s_dec[col];
                    rowsum[mi * 2 + (r >> 1)] += tanh_fast(x) * s_wout[col];
                }
    }

    // reduce rowsum: over lane&3 (shfl), then over nw (smem)
#pragma unroll
    for (int i = 0; i < 4; i++) {
        float v = rowsum[i];
        v += __shfl_xor_sync(0xffffffffu, v, 1);
        v += __shfl_xor_sync(0xffffffffu, v, 2);
        rowsum[i] = v;
    }
    if ((lane & 3) == 0) {
#pragma unroll
        for (int i = 0; i < 4; i++) {
            int row = mw * 32 + (i >> 1) * 16 + (lane >> 2) + (i & 1) * 8;
            s_part[nw * 128 + row] = rowsum[i];
        }
    }
    __syncthreads();
    if (tid < 128)
        logits[rowbase + tid] = s_part[tid] + s_part[128 + tid];
}

// ---------------------------------------------------------------------------
// Kernel 3: masked softmax over S, in place
// ---------------------------------------------------------------------------
__global__ void softmax_kernel(const int* __restrict__ mask,
                               float* __restrict__ probs) {
    int b = blockIdx.x;
    int t = threadIdx.x;
    __shared__ float red[32];
    float l[4];
#pragma unroll
    for (int i = 0; i < 4; i++) {
        int s = t + i * 1024;
        float v = probs[(long)b * S + s];
        l[i] = (mask[(long)b * S + s] == 0) ? NEGV : v;
    }
    float m = fmaxf(fmaxf(l[0], l[1]), fmaxf(l[2], l[3]));
#pragma unroll
    for (int off = 16; off > 0; off >>= 1)
        m = fmaxf(m, __shfl_xor_sync(0xffffffffu, m, off));
    if ((t & 31) == 0) red[t >> 5] = m;
    __syncthreads();
    if (t < 32) {
        float v = red[t];
#pragma unroll
        for (int off = 16; off > 0; off >>= 1)
            v = fmaxf(v, __shfl_xor_sync(0xffffffffu, v, off));
        red[t] = v;
    }
    __syncthreads();
    m = red[0];
    __syncthreads();
    float e[4];
    float sum = 0.f;
#pragma unroll
    for (int i = 0; i < 4; i++) { e[i] = expf(l[i] - m); sum += e[i]; }
#pragma unroll
    for (int off = 16; off > 0; off >>= 1)
        sum += __shfl_xor_sync(0xffffffffu, sum, off);
    if ((t & 31) == 0) red[t >> 5] = sum;
    __syncthreads();
    if (t < 32) {
        float v = red[t];
#pragma unroll
        for (int off = 16; off > 0; off >>= 1)
            v += __shfl_xor_sync(0xffffffffu, v, off);
        red[t] = v;
    }
    __syncthreads();
    float inv = 1.f / red[0];
#pragma unroll
    for (int i = 0; i < 4; i++)
        probs[(long)b * S + t + i * 1024] = e[i] * inv;
}

// ---------------------------------------------------------------------------
// Kernel 4: partial attn over 128-row s-chunks, float4 per thread
// ---------------------------------------------------------------------------
__global__ void attn_part_kernel(const float* __restrict__ enc,
                                 const float* __restrict__ probs) {
    int sc = blockIdx.x & 31;
    int b  = blockIdx.x >> 5;
    int t  = threadIdx.x;   // 0..127
    __shared__ float p_s[128];
    p_s[t] = probs[(long)b * S + sc * 128 + t];
    __syncthreads();
    const float4* encp = (const float4*)(enc + ((long)b * S + (long)sc * 128) * E) + t;
    float4 acc = make_float4(0.f, 0.f, 0.f, 0.f);
#pragma unroll 8
    for (int s = 0; s < 128; s++) {
        float4 v = encp[(long)s * (E / 4)];
        float p = p_s[s];
        acc.x += p * v.x; acc.y += p * v.y;
        acc.z += p * v.z; acc.w += p * v.w;
    }
    ((float4*)g_attn_part)[((long)b * 32 + sc) * (E / 4) + t] = acc;
}

// ---------------------------------------------------------------------------
// Kernel 5: fixed-order reduction -> attn (float4)
// ---------------------------------------------------------------------------
__global__ void attn_reduce_kernel(float* __restrict__ attn) {
    int b = blockIdx.x;
    int t = threadIdx.x;   // 0..127
    float4 s = make_float4(0.f, 0.f, 0.f, 0.f);
#pragma unroll
    for (int c = 0; c < 32; c++) {
        float4 v = ((const float4*)g_attn_part)[((long)b * 32 + c) * (E / 4) + t];
        s.x += v.x; s.y += v.y; s.z += v.z; s.w += v.w;
    }
    ((float4*)attn)[b * (E / 4) + t] = s;
}

// ---------------------------------------------------------------------------
extern "C" void kernel_launch(void* const* d_in, const int* in_sizes, int n_in,
                              void* d_out, int out_size) {
    const float* enc   = (const float*)d_in[0];
    const float* dec   = (const float*)d_in[1];
    const int*   mask  = (const int*)  d_in[2];
    const float* W_enc = (const float*)d_in[3];
    const float* W_dec = (const float*)d_in[4];
    const float* W_out = (const float*)d_in[5];

    float* attn  = (float*)d_out;       // [B,E]
    float* probs = attn + B * E;        // [B,S] (logits written in place)

    cudaFuncSetAttribute(logits_mma_kernel,
                         cudaFuncAttributeMaxDynamicSharedMemorySize, SMF_TOTAL);

    wsplit_kernel<<<512, 256>>>(W_enc);
    decode_kernel<<<B, 512>>>(dec, W_dec);
    logits_mma_kernel<<<B * (S / 128), 256, SMF_TOTAL>>>(enc, W_out, probs);
    softmax_kernel<<<B, 1024>>>(mask, probs);
    attn_part_kernel<<<B * 32, 128>>>(enc, probs);
    attn_reduce_kernel<<<B, 128>>>(attn);
}

// round 6
// speedup vs baseline: 2.3647x; 2.3543x over previous
#include <cuda_runtime.h>
#include <cuda_fp16.h>
#include <math.h>
#include <cstdint>

#define B 64
#define S 4096
#define E 512
#define D 512
#define H 512
#define NEGV (-1.0e9f)

// ---------------------------------------------------------------------------
// Scratch (no cudaMalloc allowed)
// ---------------------------------------------------------------------------
__device__ float g_decoded[B * H];            // 128 KB
__device__ float g_attn_part[B * 32 * E];     // 4 MB
// W_enc^T split hi/lo fp16, packed in m16n8k16 B-fragment order:
// uint4 { hi(k0,k0+1), hi(k0+8,k0+9), lo(k0,k0+1), lo(k0+8,k0+9) }
// at index (k16*64 + n8)*32 + lane, k0 = k16*16 + (lane&3)*2, n = n8*8 + lane/4
__device__ uint4 g_WBh[32 * 64 * 32];         // 1 MB

// ---------------------------------------------------------------------------
// helpers
// ---------------------------------------------------------------------------
__device__ __forceinline__ uint32_t smem_u32(const void* p) {
    uint32_t a;
    asm("{ .reg .u64 t; cvta.to.shared.u64 t, %1; cvt.u32.u64 %0, t; }"
        : "=r"(a) : "l"(p));
    return a;
}
__device__ __forceinline__ float tanh_fast(float x) {
    float e;
    asm("ex2.approx.f32 %0, %1;" : "=f"(e) : "f"(x * 2.8853900817779268f));
    float r;
    asm("rcp.approx.f32 %0, %1;" : "=f"(r) : "f"(e + 1.0f));
    return fmaf(-2.0f, r, 1.0f);
}
// split float2 -> fp16 hi pair + fp16 lo pair (packed half2 as u32)
__device__ __forceinline__ void split_h2(float x, float y,
                                         uint32_t& hi, uint32_t& lo) {
    half2 h2 = __floats2half2_rn(x, y);
    float2 hf = __half22float2(h2);
    half2 l2 = __floats2half2_rn(x - hf.x, y - hf.y);
    hi = *(uint32_t*)&h2;
    lo = *(uint32_t*)&l2;
}
#define MMA_F16(d, a, b0, b1) \
    asm volatile( \
        "mma.sync.aligned.m16n8k16.row.col.f32.f16.f16.f32 " \
        "{%0,%1,%2,%3}, {%4,%5,%6,%7}, {%8,%9}, {%0,%1,%2,%3};" \
        : "+f"((d)[0]), "+f"((d)[1]), "+f"((d)[2]), "+f"((d)[3]) \
        : "r"((a)[0]), "r"((a)[1]), "r"((a)[2]), "r"((a)[3]), \
          "r"(b0), "r"(b1))

#define CP_ASYNC16(dst, src) \
    asm volatile("cp.async.cg.shared.global [%0], [%1], 16;" \
                 :: "r"(dst), "l"(src) : "memory")
#define CP_COMMIT()  asm volatile("cp.async.commit_group;" ::: "memory")
#define CP_WAIT(n)   asm volatile("cp.async.wait_group %0;" :: "n"(n) : "memory")

// A smem swizzle: float index for logical (row, col) in a 128x32 tile
__device__ __forceinline__ int a_idx(int r, int c) {
    return r * 32 + ((((c >> 2) ^ (r & 7)) << 2) | (c & 3));
}

// ---------------------------------------------------------------------------
// Kernel 0: W_enc [E,H] -> g_WBh (transposed, fp16 hi/lo, fragment order)
// ---------------------------------------------------------------------------
__global__ void wsplit_kernel(const float* __restrict__ W_enc) {
    int idx = blockIdx.x * 256 + threadIdx.x;   // 65536 total
    int lane = idx & 31;
    int n8   = (idx >> 5) & 63;
    int k16  = idx >> 11;
    int k0 = k16 * 16 + (lane & 3) * 2;
    int n  = n8 * 8 + (lane >> 2);
    float v0 = W_enc[(k0    ) * H + n];
    float v1 = W_enc[(k0 + 1) * H + n];
    float v2 = W_enc[(k0 + 8) * H + n];
    float v3 = W_enc[(k0 + 9) * H + n];
    uint4 o;
    split_h2(v0, v1, o.x, o.z);
    split_h2(v2, v3, o.y, o.w);
    g_WBh[idx] = o;
}

// ---------------------------------------------------------------------------
// Kernel 1: decoded[b,h] = dec[b,:] @ W_dec[:,h]
// ---------------------------------------------------------------------------
__global__ void decode_kernel(const float* __restrict__ dec,
                              const float* __restrict__ W_dec) {
    int b = blockIdx.x;
    int t = threadIdx.x;
    __shared__ float ds[D];
    ds[t] = dec[b * D + t];
    __syncthreads();
    float sum = 0.f;
#pragma unroll 8
    for (int d = 0; d < D; d++) sum += ds[d] * W_dec[d * H + t];
    g_decoded[b * H + t] = sum;
}

// ---------------------------------------------------------------------------
// Kernel 2: logits via mma.sync fp16x3
// grid = B*(S/128) = 2048 blocks, 256 threads (8 warps: 4 m-warps x 2 n-warps)
// block tile: M=128 rows, N in 4 chunks of 128 cols, K=512
// ---------------------------------------------------------------------------
__global__ void __launch_bounds__(256, 1)
logits_mma_kernel(const float* __restrict__ enc,
                  const float* __restrict__ W_out,
                  float* __restrict__ logits) {
    __shared__ float s_dec[H];
    __shared__ float s_wout[H];
    __shared__ float s_part[256];
    __shared__ __align__(128) float sA[2][128 * 32];

    int tid = threadIdx.x;
    int lane = tid & 31;
    int wid = tid >> 5;
    int mw = wid & 3;     // 0..3  -> rows mw*32..
    int nw = wid >> 2;    // 0..1  -> n8 offset nw*8 within the 128-col chunk

    int b  = blockIdx.x >> 5;
    int st = blockIdx.x & 31;
    long rowbase = (long)b * S + (long)st * 128;
    const float* encBase = enc + rowbase * E;

    for (int i = tid; i < H; i += 256) {
        s_dec[i]  = g_decoded[b * H + i];
        s_wout[i] = W_out[i];
    }

    const uint4* gB = g_WBh;
    float rowsum[4] = {0.f, 0.f, 0.f, 0.f};

    // staging helper (cp.async 16B x4 per thread = one 128x32 chunk)
    auto stageA = [&](int kc, int buf) {
#pragma unroll
        for (int it = 0; it < 4; it++) {
            int fidx = tid + it * 256;          // 0..1023 float4s
            int row = fidx >> 3;
            int kw  = fidx & 7;
            const float* src = encBase + (long)row * E + kc * 32 + kw * 4;
            uint32_t dst = smem_u32(&sA[buf][row * 32 + ((kw ^ (row & 7)) << 2)]);
            CP_ASYNC16(dst, src);
        }
        CP_COMMIT();
    };

    for (int nc = 0; nc < 4; nc++) {
        float acc[2][8][4];
#pragma unroll
        for (int mi = 0; mi < 2; mi++)
#pragma unroll
            for (int j = 0; j < 8; j++)
#pragma unroll
                for (int r = 0; r < 4; r++) acc[mi][j][r] = 0.f;

        int n8base = nc * 16 + nw * 8;

        // prime B for k16 = 0
        uint4 bc[8];
#pragma unroll
        for (int j = 0; j < 8; j++)
            bc[j] = gB[(n8base + j) * 32 + lane];

        stageA(0, 0);

        for (int kc = 0; kc < 16; kc++) {
            if (kc < 15) { stageA(kc + 1, (kc + 1) & 1); CP_WAIT(1); }
            else         { CP_WAIT(0); }
            __syncthreads();
            const float* A = sA[kc & 1];

#pragma unroll
            for (int kk = 0; kk < 2; kk++) {
                int k16 = kc * 2 + kk;
                // prefetch B for next k16
                uint4 bn[8];
                int k16n = (k16 + 1 < 32) ? k16 + 1 : 31;
#pragma unroll
                for (int j = 0; j < 8; j++)
                    bn[j] = gB[(k16n * 64 + n8base + j) * 32 + lane];

                // A fragments (hi & lo) for 2 m16 tiles, fp16 split in regs
                uint32_t aH[2][4], aL[2][4];
                int c0 = kk * 16 + (lane & 3) * 2;
#pragma unroll
                for (int mi = 0; mi < 2; mi++) {
                    int r0 = mw * 32 + mi * 16 + (lane >> 2);
                    int r1 = r0 + 8;
                    // pairs (c0,c0+1) and (c0+8,c0+9) are contiguous in smem
                    float2 v00 = *(const float2*)&A[a_idx(r0, c0)];
                    float2 v10 = *(const float2*)&A[a_idx(r1, c0)];
                    float2 v01 = *(const float2*)&A[a_idx(r0, c0 + 8)];
                    float2 v11 = *(const float2*)&A[a_idx(r1, c0 + 8)];
                    split_h2(v00.x, v00.y, aH[mi][0], aL[mi][0]);
                    split_h2(v10.x, v10.y, aH[mi][1], aL[mi][1]);
                    split_h2(v01.x, v01.y, aH[mi][2], aL[mi][2]);
                    split_h2(v11.x, v11.y, aH[mi][3], aL[mi][3]);
                }

                // hi*hi
#pragma unroll
                for (int mi = 0; mi < 2; mi++)
#pragma unroll
                    for (int j = 0; j < 8; j++)
                        MMA_F16(acc[mi][j], aH[mi], bc[j].x, bc[j].y);
                // lo*hi
#pragma unroll
                for (int mi = 0; mi < 2; mi++)
#pragma unroll
                    for (int j = 0; j < 8; j++)
                        MMA_F16(acc[mi][j], aL[mi], bc[j].x, bc[j].y);
                // hi*lo
#pragma unroll
                for (int mi = 0; mi < 2; mi++)
#pragma unroll
                    for (int j = 0; j < 8; j++)
                        MMA_F16(acc[mi][j], aH[mi], bc[j].z, bc[j].w);

#pragma unroll
                for (int j = 0; j < 8; j++) bc[j] = bn[j];
            }
            __syncthreads();
        }

        // epilogue for this N-chunk: tanh(acc + dec) * wout -> rowsum
#pragma unroll
        for (int mi = 0; mi < 2; mi++)
#pragma unroll
            for (int j = 0; j < 8; j++)
#pragma unroll
                for (int r = 0; r < 4; r++) {
                    int col = nc * 128 + nw * 64 + j * 8 + (lane & 3) * 2 + (r & 1);
                    float x = acc[mi][j][r] + s_dec[col];
                    rowsum[mi * 2 + (r >> 1)] += tanh_fast(x) * s_wout[col];
                }
    }

    // reduce rowsum: over lane&3 (shfl), then over nw (smem)
#pragma unroll
    for (int i = 0; i < 4; i++) {
        float v = rowsum[i];
        v += __shfl_xor_sync(0xffffffffu, v, 1);
        v += __shfl_xor_sync(0xffffffffu, v, 2);
        rowsum[i] = v;
    }
    if ((lane & 3) == 0) {
#pragma unroll
        for (int i = 0; i < 4; i++) {
            int row = mw * 32 + (i >> 1) * 16 + (lane >> 2) + (i & 1) * 8;
            s_part[nw * 128 + row] = rowsum[i];
        }
    }
    __syncthreads();
    if (tid < 128)
        logits[rowbase + tid] = s_part[tid] + s_part[128 + tid];
}

// ---------------------------------------------------------------------------
// Kernel 3: masked softmax over S, in place
// ---------------------------------------------------------------------------
__global__ void softmax_kernel(const int* __restrict__ mask,
                               float* __restrict__ probs) {
    int b = blockIdx.x;
    int t = threadIdx.x;
    __shared__ float red[32];
    float l[4];
#pragma unroll
    for (int i = 0; i < 4; i++) {
        int s = t + i * 1024;
        float v = probs[(long)b * S + s];
        l[i] = (mask[(long)b * S + s] == 0) ? NEGV : v;
    }
    float m = fmaxf(fmaxf(l[0], l[1]), fmaxf(l[2], l[3]));
#pragma unroll
    for (int off = 16; off > 0; off >>= 1)
        m = fmaxf(m, __shfl_xor_sync(0xffffffffu, m, off));
    if ((t & 31) == 0) red[t >> 5] = m;
    __syncthreads();
    if (t < 32) {
        float v = red[t];
#pragma unroll
        for (int off = 16; off > 0; off >>= 1)
            v = fmaxf(v, __shfl_xor_sync(0xffffffffu, v, off));
        red[t] = v;
    }
    __syncthreads();
    m = red[0];
    __syncthreads();
    float e[4];
    float sum = 0.f;
#pragma unroll
    for (int i = 0; i < 4; i++) { e[i] = expf(l[i] - m); sum += e[i]; }
#pragma unroll
    for (int off = 16; off > 0; off >>= 1)
        sum += __shfl_xor_sync(0xffffffffu, sum, off);
    if ((t & 31) == 0) red[t >> 5] = sum;
    __syncthreads();
    if (t < 32) {
        float v = red[t];
#pragma unroll
        for (int off = 16; off > 0; off >>= 1)
            v += __shfl_xor_sync(0xffffffffu, v, off);
        red[t] = v;
    }
    __syncthreads();
    float inv = 1.f / red[0];
#pragma unroll
    for (int i = 0; i < 4; i++)
        probs[(long)b * S + t + i * 1024] = e[i] * inv;
}

// ---------------------------------------------------------------------------
// Kernel 4: partial attn over 128-row s-chunks, float4 per thread
// ---------------------------------------------------------------------------
__global__ void attn_part_kernel(const float* __restrict__ enc,
                                 const float* __restrict__ probs) {
    int sc = blockIdx.x & 31;
    int b  = blockIdx.x >> 5;
    int t  = threadIdx.x;   // 0..127
    __shared__ float p_s[128];
    p_s[t] = probs[(long)b * S + sc * 128 + t];
    __syncthreads();
    const float4* encp = (const float4*)(enc + ((long)b * S + (long)sc * 128) * E) + t;
    float4 acc = make_float4(0.f, 0.f, 0.f, 0.f);
#pragma unroll 8
    for (int s = 0; s < 128; s++) {
        float4 v = encp[(long)s * (E / 4)];
        float p = p_s[s];
        acc.x += p * v.x; acc.y += p * v.y;
        acc.z += p * v.z; acc.w += p * v.w;
    }
    ((float4*)g_attn_part)[((long)b * 32 + sc) * (E / 4) + t] = acc;
}

// ---------------------------------------------------------------------------
// Kernel 5: fixed-order reduction -> attn (float4)
// ---------------------------------------------------------------------------
__global__ void attn_reduce_kernel(float* __restrict__ attn) {
    int b = blockIdx.x;
    int t = threadIdx.x;   // 0..127
    float4 s = make_float4(0.f, 0.f, 0.f, 0.f);
#pragma unroll
    for (int c = 0; c < 32; c++) {
        float4 v = ((const float4*)g_attn_part)[((long)b * 32 + c) * (E / 4) + t];
        s.x += v.x; s.y += v.y; s.z += v.z; s.w += v.w;
    }
    ((float4*)attn)[b * (E / 4) + t] = s;
}

// ---------------------------------------------------------------------------
extern "C" void kernel_launch(void* const* d_in, const int* in_sizes, int n_in,
                              void* d_out, int out_size) {
    const float* enc   = (const float*)d_in[0];
    const float* dec   = (const float*)d_in[1];
    const int*   mask  = (const int*)  d_in[2];
    const float* W_enc = (const float*)d_in[3];
    const float* W_dec = (const float*)d_in[4];
    const float* W_out = (const float*)d_in[5];

    float* attn  = (float*)d_out;       // [B,E]
    float* probs = attn + B * E;        // [B,S] (logits written in place)

    wsplit_kernel<<<256, 256>>>(W_enc);
    decode_kernel<<<B, 512>>>(dec, W_dec);
    logits_mma_kernel<<<B * (S / 128), 256>>>(enc, W_out, probs);
    softmax_kernel<<<B, 1024>>>(mask, probs);
    attn_part_kernel<<<B * 32, 128>>>(enc, probs);
    attn_reduce_kernel<<<B, 128>>>(attn);
}

// round 7
// speedup vs baseline: 2.5283x; 1.0692x over previous
#include <cuda_runtime.h>
#include <cuda_fp16.h>
#include <math.h>
#include <cstdint>

#define B 64
#define S 4096
#define E 512
#define D 512
#define H 512
#define NEGV (-1.0e9f)

// ---------------------------------------------------------------------------
// Scratch (no cudaMalloc allowed)
// ---------------------------------------------------------------------------
__device__ float g_decoded[B * H];            // 128 KB
__device__ float g_attn_part[B * 32 * E];     // 4 MB
// W_enc^T split hi/lo fp16, packed in m16n8k16 B-fragment order:
// uint4 { hi(k0,k0+1), hi(k0+8,k0+9), lo(k0,k0+1), lo(k0+8,k0+9) }
// at index (k16*64 + n8)*32 + lane, k0 = k16*16 + (lane&3)*2, n = n8*8 + lane/4
__device__ uint4 g_WBh[32 * 64 * 32];         // 1 MB

// ---------------------------------------------------------------------------
// helpers
// ---------------------------------------------------------------------------
__device__ __forceinline__ uint32_t smem_u32(const void* p) {
    uint32_t a;
    asm("{ .reg .u64 t; cvta.to.shared.u64 t, %1; cvt.u32.u64 %0, t; }"
        : "=r"(a) : "l"(p));
    return a;
}
__device__ __forceinline__ float tanh_fast(float x) {
    float e;
    asm("ex2.approx.f32 %0, %1;" : "=f"(e) : "f"(x * 2.8853900817779268f));
    float r;
    asm("rcp.approx.f32 %0, %1;" : "=f"(r) : "f"(e + 1.0f));
    return fmaf(-2.0f, r, 1.0f);
}
// split float2 -> fp16 hi pair + fp16 lo pair (packed half2 as u32)
__device__ __forceinline__ void split_h2(float x, float y,
                                         uint32_t& hi, uint32_t& lo) {
    half2 h2 = __floats2half2_rn(x, y);
    float2 hf = __half22float2(h2);
    half2 l2 = __floats2half2_rn(x - hf.x, y - hf.y);
    hi = *(uint32_t*)&h2;
    lo = *(uint32_t*)&l2;
}
#define MMA_F16(d, a, b0, b1) \
    asm volatile( \
        "mma.sync.aligned.m16n8k16.row.col.f32.f16.f16.f32 " \
        "{%0,%1,%2,%3}, {%4,%5,%6,%7}, {%8,%9}, {%0,%1,%2,%3};" \
        : "+f"((d)[0]), "+f"((d)[1]), "+f"((d)[2]), "+f"((d)[3]) \
        : "r"((a)[0]), "r"((a)[1]), "r"((a)[2]), "r"((a)[3]), \
          "r"(b0), "r"(b1))

#define CP_ASYNC16(dst, src) \
    asm volatile("cp.async.cg.shared.global [%0], [%1], 16;" \
                 :: "r"(dst), "l"(src) : "memory")
#define CP_COMMIT()  asm volatile("cp.async.commit_group;" ::: "memory")
#define CP_WAIT(n)   asm volatile("cp.async.wait_group %0;" :: "n"(n) : "memory")

// A smem swizzle: float index for logical (row, col) in a 128x32 tile
__device__ __forceinline__ int a_idx(int r, int c) {
    return r * 32 + ((((c >> 2) ^ (r & 7)) << 2) | (c & 3));
}

// ---------------------------------------------------------------------------
// Kernel 0: W_enc [E,H] -> g_WBh (transposed, fp16 hi/lo, fragment order)
// ---------------------------------------------------------------------------
__global__ void wsplit_kernel(const float* __restrict__ W_enc) {
    int idx = blockIdx.x * 256 + threadIdx.x;   // 65536 total
    int lane = idx & 31;
    int n8   = (idx >> 5) & 63;
    int k16  = idx >> 11;
    int k0 = k16 * 16 + (lane & 3) * 2;
    int n  = n8 * 8 + (lane >> 2);
    float v0 = W_enc[(k0    ) * H + n];
    float v1 = W_enc[(k0 + 1) * H + n];
    float v2 = W_enc[(k0 + 8) * H + n];
    float v3 = W_enc[(k0 + 9) * H + n];
    uint4 o;
    split_h2(v0, v1, o.x, o.z);
    split_h2(v2, v3, o.y, o.w);
    g_WBh[idx] = o;
}

// ---------------------------------------------------------------------------
// Kernel 1: decoded[b,h] = dec[b,:] @ W_dec[:,h]
// ---------------------------------------------------------------------------
__global__ void decode_kernel(const float* __restrict__ dec,
                              const float* __restrict__ W_dec) {
    int b = blockIdx.x;
    int t = threadIdx.x;
    __shared__ float ds[D];
    ds[t] = dec[b * D + t];
    __syncthreads();
    float sum = 0.f;
#pragma unroll 8
    for (int d = 0; d < D; d++) sum += ds[d] * W_dec[d * H + t];
    g_decoded[b * H + t] = sum;
}

// ---------------------------------------------------------------------------
// Kernel 2: logits via mma.sync fp16x3, 2 CTAs/SM
// grid = B*(S/128) = 2048 blocks, 256 threads (8 warps: 4 m-warps x 2 n-warps)
// block tile: M=128 rows, N in 4 chunks of 128 cols, K=512
// ---------------------------------------------------------------------------
__global__ void __launch_bounds__(256, 2)
logits_mma_kernel(const float* __restrict__ enc,
                  const float* __restrict__ W_out,
                  float* __restrict__ logits) {
    __shared__ float s_dec[H];
    __shared__ float s_wout[H];
    __shared__ float s_part[256];
    __shared__ __align__(128) float sA[2][128 * 32];

    int tid = threadIdx.x;
    int lane = tid & 31;
    int wid = tid >> 5;
    int mw = wid & 3;     // 0..3  -> rows mw*32..
    int nw = wid >> 2;    // 0..1  -> n8 offset nw*8 within the 128-col chunk

    int b  = blockIdx.x >> 5;
    int st = blockIdx.x & 31;
    long rowbase = (long)b * S + (long)st * 128;
    const float* encBase = enc + rowbase * E;

    for (int i = tid; i < H; i += 256) {
        s_dec[i]  = g_decoded[b * H + i];
        s_wout[i] = W_out[i];
    }

    const uint4* gB = g_WBh;
    float rowsum[4] = {0.f, 0.f, 0.f, 0.f};

    // staging helper (cp.async 16B x4 per thread = one 128x32 chunk)
    auto stageA = [&](int kc, int buf) {
#pragma unroll
        for (int it = 0; it < 4; it++) {
            int fidx = tid + it * 256;          // 0..1023 float4s
            int row = fidx >> 3;
            int kw  = fidx & 7;
            const float* src = encBase + (long)row * E + kc * 32 + kw * 4;
            uint32_t dst = smem_u32(&sA[buf][row * 32 + ((kw ^ (row & 7)) << 2)]);
            CP_ASYNC16(dst, src);
        }
        CP_COMMIT();
    };

    for (int nc = 0; nc < 4; nc++) {
        float acc[2][8][4];
#pragma unroll
        for (int mi = 0; mi < 2; mi++)
#pragma unroll
            for (int j = 0; j < 8; j++)
#pragma unroll
                for (int r = 0; r < 4; r++) acc[mi][j][r] = 0.f;

        int n8base = nc * 16 + nw * 8;

        stageA(0, 0);

        for (int kc = 0; kc < 16; kc++) {
            if (kc < 15) { stageA(kc + 1, (kc + 1) & 1); CP_WAIT(1); }
            else         { CP_WAIT(0); }
            __syncthreads();
            const float* A = sA[kc & 1];

#pragma unroll
            for (int kk = 0; kk < 2; kk++) {
                int k16 = kc * 2 + kk;
                // B fragments for this k16 (no double-buffer; TLP hides latency)
                uint4 bc[8];
#pragma unroll
                for (int j = 0; j < 8; j++)
                    bc[j] = gB[(k16 * 64 + n8base + j) * 32 + lane];

                // A fragments (hi & lo) for 2 m16 tiles, fp16 split in regs
                uint32_t aH[2][4], aL[2][4];
                int c0 = kk * 16 + (lane & 3) * 2;
#pragma unroll
                for (int mi = 0; mi < 2; mi++) {
                    int r0 = mw * 32 + mi * 16 + (lane >> 2);
                    int r1 = r0 + 8;
                    // pairs (c0,c0+1) and (c0+8,c0+9) are contiguous in smem
                    float2 v00 = *(const float2*)&A[a_idx(r0, c0)];
                    float2 v10 = *(const float2*)&A[a_idx(r1, c0)];
                    float2 v01 = *(const float2*)&A[a_idx(r0, c0 + 8)];
                    float2 v11 = *(const float2*)&A[a_idx(r1, c0 + 8)];
                    split_h2(v00.x, v00.y, aH[mi][0], aL[mi][0]);
                    split_h2(v10.x, v10.y, aH[mi][1], aL[mi][1]);
                    split_h2(v01.x, v01.y, aH[mi][2], aL[mi][2]);
                    split_h2(v11.x, v11.y, aH[mi][3], aL[mi][3]);
                }

                // hi*hi
#pragma unroll
                for (int mi = 0; mi < 2; mi++)
#pragma unroll
                    for (int j = 0; j < 8; j++)
                        MMA_F16(acc[mi][j], aH[mi], bc[j].x, bc[j].y);
                // lo*hi
#pragma unroll
                for (int mi = 0; mi < 2; mi++)
#pragma unroll
                    for (int j = 0; j < 8; j++)
                        MMA_F16(acc[mi][j], aL[mi], bc[j].x, bc[j].y);
                // hi*lo
#pragma unroll
                for (int mi = 0; mi < 2; mi++)
#pragma unroll
                    for (int j = 0; j < 8; j++)
                        MMA_F16(acc[mi][j], aH[mi], bc[j].z, bc[j].w);
            }
            __syncthreads();
        }

        // epilogue for this N-chunk: tanh(acc + dec) * wout -> rowsum
#pragma unroll
        for (int mi = 0; mi < 2; mi++)
#pragma unroll
            for (int j = 0; j < 8; j++)
#pragma unroll
                for (int r = 0; r < 4; r++) {
                    int col = nc * 128 + nw * 64 + j * 8 + (lane & 3) * 2 + (r & 1);
                    float x = acc[mi][j][r] + s_dec[col];
                    rowsum[mi * 2 + (r >> 1)] += tanh_fast(x) * s_wout[col];
                }
    }

    // reduce rowsum: over lane&3 (shfl), then over nw (smem)
#pragma unroll
    for (int i = 0; i < 4; i++) {
        float v = rowsum[i];
        v += __shfl_xor_sync(0xffffffffu, v, 1);
        v += __shfl_xor_sync(0xffffffffu, v, 2);
        rowsum[i] = v;
    }
    if ((lane & 3) == 0) {
#pragma unroll
        for (int i = 0; i < 4; i++) {
            int row = mw * 32 + (i >> 1) * 16 + (lane >> 2) + (i & 1) * 8;
            s_part[nw * 128 + row] = rowsum[i];
        }
    }
    __syncthreads();
    if (tid < 128)
        logits[rowbase + tid] = s_part[tid] + s_part[128 + tid];
}

// ---------------------------------------------------------------------------
// Kernel 3: masked softmax over S, in place
// ---------------------------------------------------------------------------
__global__ void softmax_kernel(const int* __restrict__ mask,
                               float* __restrict__ probs) {
    int b = blockIdx.x;
    int t = threadIdx.x;
    __shared__ float red[32];
    float l[4];
#pragma unroll
    for (int i = 0; i < 4; i++) {
        int s = t + i * 1024;
        float v = probs[(long)b * S + s];
        l[i] = (mask[(long)b * S + s] == 0) ? NEGV : v;
    }
    float m = fmaxf(fmaxf(l[0], l[1]), fmaxf(l[2], l[3]));
#pragma unroll
    for (int off = 16; off > 0; off >>= 1)
        m = fmaxf(m, __shfl_xor_sync(0xffffffffu, m, off));
    if ((t & 31) == 0) red[t >> 5] = m;
    __syncthreads();
    if (t < 32) {
        float v = red[t];
#pragma unroll
        for (int off = 16; off > 0; off >>= 1)
            v = fmaxf(v, __shfl_xor_sync(0xffffffffu, v, off));
        red[t] = v;
    }
    __syncthreads();
    m = red[0];
    __syncthreads();
    float e[4];
    float sum = 0.f;
#pragma unroll
    for (int i = 0; i < 4; i++) { e[i] = expf(l[i] - m); sum += e[i]; }
#pragma unroll
    for (int off = 16; off > 0; off >>= 1)
        sum += __shfl_xor_sync(0xffffffffu, sum, off);
    if ((t & 31) == 0) red[t >> 5] = sum;
    __syncthreads();
    if (t < 32) {
        float v = red[t];
#pragma unroll
        for (int off = 16; off > 0; off >>= 1)
            v += __shfl_xor_sync(0xffffffffu, v, off);
        red[t] = v;
    }
    __syncthreads();
    float inv = 1.f / red[0];
#pragma unroll
    for (int i = 0; i < 4; i++)
        probs[(long)b * S + t + i * 1024] = e[i] * inv;
}

// ---------------------------------------------------------------------------
// Kernel 4: partial attn over 128-row s-chunks, float4 per thread
// ---------------------------------------------------------------------------
__global__ void attn_part_kernel(const float* __restrict__ enc,
                                 const float* __restrict__ probs) {
    int sc = blockIdx.x & 31;
    int b  = blockIdx.x >> 5;
    int t  = threadIdx.x;   // 0..127
    __shared__ float p_s[128];
    p_s[t] = probs[(long)b * S + sc * 128 + t];
    __syncthreads();
    const float4* encp = (const float4*)(enc + ((long)b * S + (long)sc * 128) * E) + t;
    float4 acc = make_float4(0.f, 0.f, 0.f, 0.f);
#pragma unroll 8
    for (int s = 0; s < 128; s++) {
        float4 v = encp[(long)s * (E / 4)];
        float p = p_s[s];
        acc.x += p * v.x; acc.y += p * v.y;
        acc.z += p * v.z; acc.w += p * v.w;
    }
    ((float4*)g_attn_part)[((long)b * 32 + sc) * (E / 4) + t] = acc;
}

// ---------------------------------------------------------------------------
// Kernel 5: fixed-order reduction -> attn (float4)
// ---------------------------------------------------------------------------
__global__ void attn_reduce_kernel(float* __restrict__ attn) {
    int b = blockIdx.x;
    int t = threadIdx.x;   // 0..127
    float4 s = make_float4(0.f, 0.f, 0.f, 0.f);
#pragma unroll
    for (int c = 0; c < 32; c++) {
        float4 v = ((const float4*)g_attn_part)[((long)b * 32 + c) * (E / 4) + t];
        s.x += v.x; s.y += v.y; s.z += v.z; s.w += v.w;
    }
    ((float4*)attn)[b * (E / 4) + t] = s;
}

// ---------------------------------------------------------------------------
extern "C" void kernel_launch(void* const* d_in, const int* in_sizes, int n_in,
                              void* d_out, int out_size) {
    const float* enc   = (const float*)d_in[0];
    const float* dec   = (const float*)d_in[1];
    const int*   mask  = (const int*)  d_in[2];
    const float* W_enc = (const float*)d_in[3];
    const float* W_dec = (const float*)d_in[4];
    const float* W_out = (const float*)d_in[5];

    float* attn  = (float*)d_out;       // [B,E]
    float* probs = attn + B * E;        // [B,S] (logits written in place)

    wsplit_kernel<<<256, 256>>>(W_enc);
    decode_kernel<<<B, 512>>>(dec, W_dec);
    logits_mma_kernel<<<B * (S / 128), 256>>>(enc, W_out, probs);
    softmax_kernel<<<B, 1024>>>(mask, probs);
    attn_part_kernel<<<B * 32, 128>>>(enc, probs);
    attn_reduce_kernel<<<B, 128>>>(attn);
}